// round 8
// baseline (speedup 1.0000x reference)
#include <cuda_runtime.h>
#include <cuda_bf16.h>
#include <math.h>
#include <stdint.h>

// ---------------------------------------------------------------------------
// Static device scratch
// ---------------------------------------------------------------------------
__device__ float d_g0[5*12000];                 // stage0 g-vectors at subsampled positions
__device__ float d_qkv1[2*6*1504*768];          // stage1 q|k|v padded grid; v cols = 256+o*4+m
__device__ float d_o1raw[2*2*750*128];
__device__ float d_qkv2[2*2*754*96];            // v cols = 32+o*4+m
__device__ float d_out2[2*750*16];

__device__ __nv_bfloat16 d_W1bh[768*64];        // stage1 fused weights [n][k] bf16 hi
__device__ __nv_bfloat16 d_W1bl[768*64];        // lo
__device__ float d_Wcat2[128*96];

__device__ float d_S0part[48*30];               // stage0 low-rank stats partials per k1 block

// accumulators zeroed by k1 block 0 each run:
// [30,158)=sum1, [158,286)=sumsq1, [286,302)=sum2, [302,318)=sumsq2
__device__ float d_stats[318];
#define P_SUM1   (d_stats + 30)
#define P_SUMSQ1 (d_stats + 158)
#define P_SUM2   (d_stats + 286)
#define P_SUMSQ2 (d_stats + 302)

__device__ __forceinline__ void mma_bf16(float4& c,
    uint32_t a0, uint32_t a1, uint32_t a2, uint32_t a3,
    uint32_t b0, uint32_t b1)
{
    asm volatile(
        "mma.sync.aligned.m16n8k16.row.col.f32.bf16.bf16.f32 "
        "{%0,%1,%2,%3},{%4,%5,%6,%7},{%8,%9},{%0,%1,%2,%3};"
        : "+f"(c.x), "+f"(c.y), "+f"(c.z), "+f"(c.w)
        : "r"(a0), "r"(a1), "r"(a2), "r"(a3), "r"(b0), "r"(b1));
}

__device__ __forceinline__ void ldsm_x4(uint32_t& r0, uint32_t& r1, uint32_t& r2, uint32_t& r3,
                                        uint32_t addr)
{
    asm volatile("ldmatrix.sync.aligned.m8n8.x4.shared.b16 {%0,%1,%2,%3}, [%4];"
        : "=r"(r0), "=r"(r1), "=r"(r2), "=r"(r3) : "r"(addr));
}

// ---------------------------------------------------------------------------
// K1 mega: grid 64 blocks x 256 threads.
// Blocks 0..47: stage0 attention (4 positions/thread) -> g0 + S0 partials.
//               Block 0 also zeroes sum/sumsq accumulators.
// Blocks 48..63: weight conversion (stage1 bf16 hi/lo + stage2 fp32).
// ---------------------------------------------------------------------------
__global__ void k1_mega(const float* x,
                        const float* p0_q, const float* p0_k,
                        const float* p1_q, const float* p1_k, const float* p1_v,
                        const float* p2_q, const float* p2_k, const float* p2_v)
{
    int bid = blockIdx.x;
    int t = threadIdx.x;

    if (bid >= 48) {
        int blk = bid - 48;
        // W1: 49152 elems, 3072 per block; [n=768][k=64], col map q|k|v-interleaved
        #pragma unroll
        for (int u = 0; u < 12; u++) {
            int idx = blk*3072 + u*256 + t;
            int j = idx / 64, c = idx % 64;
            float v;
            if (j < 128)       v = p1_q[c*128 + j];
            else if (j < 256)  v = p1_k[c*128 + (j-128)];
            else { int o = (j-256) >> 2, m = (j-256) & 3; v = p1_v[(m*64+c)*128 + o]; }
            __nv_bfloat16 hi = __float2bfloat16_rn(v);
            d_W1bh[idx] = hi;
            d_W1bl[idx] = __float2bfloat16_rn(v - __bfloat162float(hi));
        }
        // Wcat2: 12288 elems, 768 per block
        #pragma unroll
        for (int u = 0; u < 3; u++) {
            int idx = blk*768 + u*256 + t;
            int c = idx / 96, j = idx % 96;
            float v;
            if (j < 16)       v = p2_q[c*16 + j];
            else if (j < 32)  v = p2_k[c*16 + (j-16)];
            else { int o = (j-32) >> 2, m = (j-32) & 3; v = p2_v[(m*128+c)*16 + o]; }
            d_Wcat2[idx] = v;
        }
        return;
    }

    // stats blocks
    if (bid == 0)
        for (int i = t; i < 288; i += 256) d_stats[30 + i] = 0.f;

    int b = bid / 24, rem = bid % 24, h = rem / 3, blk = rem % 3;

    __shared__ float sC0;
    if (t < 32) {
        float v = p0_q[t]*p0_k[t] + p0_q[t+32]*p0_k[t+32];
        #pragma unroll
        for (int off = 16; off; off >>= 1) v += __shfl_xor_sync(0xffffffffu, v, off);
        if (t == 0) sC0 = v;
    }
    __syncthreads();
    float C0 = sC0;

    const float* xr = x + (b*8 + h) * 3000;
    float st[20];
    #pragma unroll
    for (int i = 0; i < 20; i++) st[i] = 0.f;

    for (int kk = 0; kk < 4; kk++) {
        int w = blk*1024 + kk*256 + t;
        if (w >= 3000) continue;
        float xc = xr[w];
        float xl[5], sc[5];
        float mx = -1e30f;
        #pragma unroll
        for (int l = 0; l < 5; l++) {
            int c = w + l - 2;
            xl[l] = (c >= 0 && c < 3000) ? xr[c] : 0.f;
            sc[l] = xc * xl[l] * C0;
            mx = fmaxf(mx, sc[l]);
        }
        float s = 0.f;
        #pragma unroll
        for (int l = 0; l < 5; l++) { sc[l] = __expf(sc[l]-mx); s += sc[l]; }
        float inv = 1.f / s;
        float g[5];
        #pragma unroll
        for (int l = 0; l < 5; l++) g[l] = sc[l] * inv * xl[l];

        int si = 0;
        #pragma unroll
        for (int l = 0; l < 5; l++) st[si++] += g[l];
        #pragma unroll
        for (int l = 0; l < 5; l++)
            #pragma unroll
            for (int l2 = l; l2 < 5; l2++) st[si++] += g[l]*g[l2];

        if (!(h & 1) && !(w & 1)) {
            int p = b*6000 + (h>>1)*1500 + (w>>1);
            #pragma unroll
            for (int l = 0; l < 5; l++) d_g0[l*12000 + p] = g[l];
        }
    }

    #pragma unroll
    for (int i = 0; i < 20; i++)
        #pragma unroll
        for (int off = 16; off; off >>= 1)
            st[i] += __shfl_xor_sync(0xffffffffu, st[i], off);

    __shared__ float red[8][20];
    int lane = t & 31, wrp = t >> 5;
    if (lane == 0)
        for (int i = 0; i < 20; i++) red[wrp][i] = st[i];
    __syncthreads();
    if (t < 20) {
        float v = 0.f;
        #pragma unroll
        for (int j = 0; j < 8; j++) v += red[j][t];
        int slot;
        if (t < 5) slot = t;
        else {
            int k = t - 5, l = 0;
            while (k >= 5 - l) { k -= 5 - l; l++; }
            slot = 5 + l*5 + (l + k);
        }
        d_S0part[bid*30 + slot] = v;
    }
}

// ---------------------------------------------------------------------------
// K4: stage1 qkv GEMM fused with stage0 BN+ReLU (A built from g0).
// Preamble: reduce S0 partials, compute emb0/Weff0/BN coefs.
// bf16 3-term + ldmatrix, 4x2 warp layout. Zero-fills hp=0 pad rows.
// grid (94, 12), block 256.
// ---------------------------------------------------------------------------
#define K4_SMEM ((128*72 + 128*72 + 64*72 + 64*72) * 2)

__global__ void k4_gemm1(const float* p0_v, const float* p0_ea, const float* p0_eb,
                         const float* p0_em, const float* g0g, const float* b0b)
{
    extern __shared__ __nv_bfloat16 sh[];
    __nv_bfloat16* Ah = sh;
    __nv_bfloat16* Al = Ah + 128*72;
    __nv_bfloat16* Bh = Al + 128*72;
    __nv_bfloat16* Bl = Bh + 64*72;

    __shared__ float sW4[320], sScale4[64], sShift4[64], S0s[30], l0[20], e0[20];

    int tid = threadIdx.x;
    int rowBase = blockIdx.x * 128;
    int colBase = blockIdx.y * 64;

    // ---- preamble: stage0 BN coefficients ----
    if (tid < 30) {
        float s = 0.f;
        for (int j = 0; j < 48; j++) s += d_S0part[j*30 + tid];
        S0s[tid] = s;
    }
    if (tid >= 64 && tid < 84) {
        int u = tid - 64, m = u / 5, j = u % 5;
        float la = 0.f, lb = 0.f;
        for (int o = 0; o < 64; o++) {
            float em = p0_em[m*64+o];
            la += em * p0_ea[o];
            lb += em * p0_eb[o*5+j];
        }
        l0[u] = la + lb;
    }
    // ---- B tile staging (independent of preamble) ----
    {
        int n = tid >> 2;
        int seg = (tid & 3) * 16;
        const uint4* sH = (const uint4*)(d_W1bh + (colBase + n)*64 + seg);
        const uint4* sL = (const uint4*)(d_W1bl + (colBase + n)*64 + seg);
        uint4* dh = (uint4*)(Bh + n*72 + seg);
        uint4* dl = (uint4*)(Bl + n*72 + seg);
        dh[0] = sH[0]; dh[1] = sH[1];
        dl[0] = sL[0]; dl[1] = sL[1];
    }
    // ---- zero-fill share of hp=0 pad rows ----
    {
        int blockId = blockIdx.y * 94 + blockIdx.x;
        float4 z4 = make_float4(0.f,0.f,0.f,0.f);
        #pragma unroll
        for (int u = 0; u < 2; u++) {
            int f4idx = blockId*512 + u*256 + tid;
            int fidx = f4idx * 4;
            int row = fidx / 768, col = fidx % 768;
            int b = row >= 1504;
            int wp = row - b*1504;
            *(float4*)&d_qkv1[((size_t)b*9024 + wp)*768 + col] = z4;
        }
    }
    __syncthreads();
    if (tid < 5) {
        float mx = -1e30f;
        #pragma unroll
        for (int m = 0; m < 4; m++) mx = fmaxf(mx, l0[m*5+tid]);
        float e[4], s = 0.f;
        #pragma unroll
        for (int m = 0; m < 4; m++) { e[m] = __expf(l0[m*5+tid]-mx); s += e[m]; }
        #pragma unroll
        for (int m = 0; m < 4; m++) e0[m*5+tid] = e[m] / s;
    }
    __syncthreads();
    if (tid < 64) {
        int c = tid;
        float Wc[5];
        #pragma unroll
        for (int l = 0; l < 5; l++) {
            float s = 0.f;
            #pragma unroll
            for (int m = 0; m < 4; m++) s += e0[m*5+l] * p0_v[m*64+c];
            Wc[l] = s;
            sW4[l*64+c] = s;
        }
        float mn = 0.f, mq = 0.f;
        #pragma unroll
        for (int l = 0; l < 5; l++) {
            mn += S0s[l] * Wc[l];
            #pragma unroll
            for (int l2 = 0; l2 < 5; l2++) {
                int lo = l < l2 ? l : l2, hi = l < l2 ? l2 : l;
                mq += S0s[5 + lo*5 + hi] * Wc[l] * Wc[l2];
            }
        }
        float n = 48000.f;
        float mean = mn / n;
        float var  = mq / n - mean*mean;
        float sc = g0g[c] * rsqrtf(var + 1e-5f);
        sScale4[c] = sc;
        sShift4[c] = b0b[c] - mean * sc;
    }
    __syncthreads();

    // ---- A tile staging from g0 (fused stage0 BN+ReLU + bf16 split) ----
    {
        int r = tid >> 1;
        int half = (tid & 1) * 32;
        int prow = rowBase + r;
        int b = prow / 6016; int rem = prow % 6016;
        int hp = 1 + rem / 1504; int wp = rem % 1504;
        bool valid = (wp >= 2 && wp < 1502);
        __nv_bfloat16* dh = Ah + r*72 + half;
        __nv_bfloat16* dl = Al + r*72 + half;
        if (valid) {
            int p = (b*4 + (hp-1))*1500 + (wp-2);
            float g[5];
            #pragma unroll
            for (int l = 0; l < 5; l++) g[l] = d_g0[l*12000 + p];
            #pragma unroll
            for (int c2 = 0; c2 < 32; c2 += 2) {
                int c = half + c2;
                float a0 = g[0]*sW4[c]     + g[1]*sW4[64+c]   + g[2]*sW4[128+c]
                         + g[3]*sW4[192+c] + g[4]*sW4[256+c];
                float a1 = g[0]*sW4[c+1]     + g[1]*sW4[64+c+1]   + g[2]*sW4[128+c+1]
                         + g[3]*sW4[192+c+1] + g[4]*sW4[256+c+1];
                float y0 = fmaxf(fmaf(a0, sScale4[c],   sShift4[c]),   0.f);
                float y1 = fmaxf(fmaf(a1, sScale4[c+1], sShift4[c+1]), 0.f);
                __nv_bfloat16 h0 = __float2bfloat16_rn(y0);
                __nv_bfloat16 h1 = __float2bfloat16_rn(y1);
                __nv_bfloat162 hv; hv.x = h0; hv.y = h1;
                __nv_bfloat162 lv;
                lv.x = __float2bfloat16_rn(y0 - __bfloat162float(h0));
                lv.y = __float2bfloat16_rn(y1 - __bfloat162float(h1));
                *(__nv_bfloat162*)(dh + c2) = hv;
                *(__nv_bfloat162*)(dl + c2) = lv;
            }
        } else {
            uint4 z = make_uint4(0,0,0,0);
            #pragma unroll
            for (int u = 0; u < 4; u++) { ((uint4*)dh)[u] = z; ((uint4*)dl)[u] = z; }
        }
    }
    __syncthreads();

    int lane = tid & 31, wid = tid >> 5;
    int g = lane >> 2, tg = lane & 3;
    int mr   = (wid >> 1) * 32;
    int ncol = (wid & 1) * 32;

    int arow = (lane < 16) ? lane : (lane - 16);
    int acol = (lane < 16) ? 0 : 8;
    uint32_t aAddrH[2], aAddrL[2];
    #pragma unroll
    for (int mt = 0; mt < 2; mt++) {
        aAddrH[mt] = (uint32_t)__cvta_generic_to_shared(Ah + (mr + mt*16 + arow)*72 + acol);
        aAddrL[mt] = (uint32_t)__cvta_generic_to_shared(Al + (mr + mt*16 + arow)*72 + acol);
    }
    int brow = (lane & 7) + ((lane >> 4) << 3);
    int bcol = ((lane >> 3) & 1) * 8;
    uint32_t bAddrH[2], bAddrL[2];
    #pragma unroll
    for (int pr = 0; pr < 2; pr++) {
        bAddrH[pr] = (uint32_t)__cvta_generic_to_shared(Bh + (ncol + pr*16 + brow)*72 + bcol);
        bAddrL[pr] = (uint32_t)__cvta_generic_to_shared(Bl + (ncol + pr*16 + brow)*72 + bcol);
    }

    float4 acc[2][4];
    #pragma unroll
    for (int i = 0; i < 2; i++)
        #pragma unroll
        for (int j = 0; j < 4; j++) acc[i][j] = make_float4(0.f,0.f,0.f,0.f);

    #pragma unroll
    for (int ks = 0; ks < 4; ks++) {
        uint32_t koff = ks * 32;
        uint32_t ah[2][4], al[2][4], bh[2][4], bl[2][4];
        #pragma unroll
        for (int mt = 0; mt < 2; mt++) {
            ldsm_x4(ah[mt][0],ah[mt][1],ah[mt][2],ah[mt][3], aAddrH[mt] + koff);
            ldsm_x4(al[mt][0],al[mt][1],al[mt][2],al[mt][3], aAddrL[mt] + koff);
        }
        #pragma unroll
        for (int pr = 0; pr < 2; pr++) {
            ldsm_x4(bh[pr][0],bh[pr][1],bh[pr][2],bh[pr][3], bAddrH[pr] + koff);
            ldsm_x4(bl[pr][0],bl[pr][1],bl[pr][2],bl[pr][3], bAddrL[pr] + koff);
        }
        #pragma unroll
        for (int mt = 0; mt < 2; mt++)
            #pragma unroll
            for (int pr = 0; pr < 2; pr++) {
                mma_bf16(acc[mt][2*pr  ], ah[mt][0],ah[mt][1],ah[mt][2],ah[mt][3], bh[pr][0],bh[pr][1]);
                mma_bf16(acc[mt][2*pr  ], ah[mt][0],ah[mt][1],ah[mt][2],ah[mt][3], bl[pr][0],bl[pr][1]);
                mma_bf16(acc[mt][2*pr  ], al[mt][0],al[mt][1],al[mt][2],al[mt][3], bh[pr][0],bh[pr][1]);
                mma_bf16(acc[mt][2*pr+1], ah[mt][0],ah[mt][1],ah[mt][2],ah[mt][3], bh[pr][2],bh[pr][3]);
                mma_bf16(acc[mt][2*pr+1], ah[mt][0],ah[mt][1],ah[mt][2],ah[mt][3], bl[pr][2],bl[pr][3]);
                mma_bf16(acc[mt][2*pr+1], al[mt][0],al[mt][1],al[mt][2],al[mt][3], bh[pr][2],bh[pr][3]);
            }
    }

    #pragma unroll
    for (int mt = 0; mt < 2; mt++) {
        #pragma unroll
        for (int half = 0; half < 2; half++) {
            int prow = rowBase + mr + mt*16 + half*8 + g;
            int b = prow / 6016; int rem = prow % 6016;
            int hp = 1 + rem / 1504; int wp = rem % 1504;
            size_t orow = (size_t)(b*6 + hp)*1504 + wp;
            #pragma unroll
            for (int j = 0; j < 4; j++) {
                int col = colBase + ncol + j*8 + tg*2;
                float2 v = half ? make_float2(acc[mt][j].z, acc[mt][j].w)
                                : make_float2(acc[mt][j].x, acc[mt][j].y);
                *(float2*)&d_qkv1[orow*768 + col] = v;
            }
        }
    }
}

// ---------------------------------------------------------------------------
// K5: stage1 attention combine, smem-staged kv window + in-block emb1.
// 10 positions/block, 512 threads. grid (150, 4, 2).
// ---------------------------------------------------------------------------
#define K5_SMEM ((10*128 + 28*640) * 4)

__global__ void k5_attn1(const float* p1_em, const float* p1_ea, const float* p1_eb)
{
    extern __shared__ float sm5[];
    float* sq = sm5;                // [10][128]
    float* kv = sm5 + 10*128;       // [28][640]

    int w0 = blockIdx.x * 10, h = blockIdx.y, b = blockIdx.z;
    int tid = threadIdx.x, lane = tid & 31, wrp = tid >> 5;  // 16 warps
    __shared__ float ssc[10][10];
    __shared__ float cm4[10][40];
    __shared__ float sla[8], slb[20], semb1[40];

    const float* base = d_qkv1 + (size_t)b * 6 * 1504 * 768;

    // emb1 via warp-cooperative dots: 28 dots of length 128
    for (int d = wrp; d < 28; d += 16) {
        float acc = 0.f;
        if (d < 8) {
            int m = d >> 1, i = d & 1;
            #pragma unroll
            for (int u = 0; u < 4; u++) {
                int o = lane + u*32;
                acc += p1_em[m*128+o] * p1_ea[o*2+i];
            }
        } else {
            int dd = d - 8;
            int m = dd / 5, j = dd % 5;
            #pragma unroll
            for (int u = 0; u < 4; u++) {
                int o = lane + u*32;
                acc += p1_em[m*128+o] * p1_eb[o*5+j];
            }
        }
        #pragma unroll
        for (int off = 16; off; off >>= 1) acc += __shfl_xor_sync(0xffffffffu, acc, off);
        if (lane == 0) { if (d < 8) sla[d] = acc; else slb[d-8] = acc; }
    }

    // stage q rows (320 float4) and kv rows (28*160 = 4480 float4)
    for (int idx = tid; idx < 320; idx += 512) {
        int p = idx >> 5, c4 = idx & 31;
        ((float4*)sq)[p*32 + c4] =
            *(const float4*)(base + ((h+1)*1504 + (w0+2+p))*768 + c4*4);
    }
    for (int idx = tid; idx < 4480; idx += 512) {
        int r = idx / 160, c4 = idx % 160;
        int i = r / 14, jj = r % 14;
        ((float4*)(kv + r*640))[c4] =
            *(const float4*)(base + ((h+i)*1504 + (w0+jj))*768 + 128 + c4*4);
    }
    __syncthreads();

    if (tid < 10) {
        int kl = tid, i = kl / 5, j = kl % 5;
        float lg[4];
        #pragma unroll
        for (int m = 0; m < 4; m++) lg[m] = sla[m*2+i] + slb[m*5+j];
        float mx = fmaxf(fmaxf(lg[0],lg[1]), fmaxf(lg[2],lg[3]));
        float e[4], s = 0.f;
        #pragma unroll
        for (int m = 0; m < 4; m++) { e[m] = __expf(lg[m]-mx); s += e[m]; }
        #pragma unroll
        for (int m = 0; m < 4; m++) semb1[kl*4+m] = e[m] / s;
    }

    // scores: 100 (p,kl) pairs over 16 warps (smem)
    for (int pair = wrp; pair < 100; pair += 16) {
        int p = pair / 10, kl = pair % 10;
        int i = kl / 5, j = kl % 5;
        float4 q4 = ((const float4*)(sq + p*128))[lane];
        float4 k4 = ((const float4*)(kv + (i*14 + p + j)*640))[lane];
        float s = q4.x*k4.x + q4.y*k4.y + q4.z*k4.z + q4.w*k4.w;
        #pragma unroll
        for (int off = 16; off; off >>= 1) s += __shfl_xor_sync(0xffffffffu, s, off);
        if (lane == 0) ssc[p][kl] = s;
    }
    __syncthreads();
    if (tid < 10) {
        float mx = -1e30f;
        #pragma unroll
        for (int kl = 0; kl < 10; kl++) mx = fmaxf(mx, ssc[tid][kl]);
        float e[10], s = 0.f;
        #pragma unroll
        for (int kl = 0; kl < 10; kl++) { e[kl] = __expf(ssc[tid][kl]-mx); s += e[kl]; }
        float inv = 1.f / s;
        #pragma unroll
        for (int kl = 0; kl < 10; kl++) {
            float a = e[kl] * inv;
            #pragma unroll
            for (int m = 0; m < 4; m++) cm4[tid][kl*4+m] = a * semb1[kl*4+m];
        }
    }
    __syncthreads();

    int o = tid & 127;
    int ph = tid >> 7;
    float s1 = 0.f, s2 = 0.f;
    for (int p = ph; p < 10; p += 4) {
        const float* cw = cm4[p];
        float acc = 0.f;
        #pragma unroll
        for (int kl = 0; kl < 10; kl++) {
            int i = kl / 5, j = kl % 5;
            float4 v = *(const float4*)(kv + (i*14 + p + j)*640 + 128 + o*4);
            acc += cw[kl*4]*v.x + cw[kl*4+1]*v.y + cw[kl*4+2]*v.z + cw[kl*4+3]*v.w;
        }
        s1 += acc; s2 += acc*acc;
        if (!(h & 1) && !((w0+p) & 1))
            d_o1raw[((b*2 + (h>>1))*750 + ((w0+p)>>1))*128 + o] = acc;
    }
    atomicAdd(&P_SUM1[o], s1);
    atomicAdd(&P_SUMSQ1[o], s2);
}

// ---------------------------------------------------------------------------
// K8: stage2 qkv GEMM, weights staged in smem, 16 positions/block.
// grid (48, 2, 2), block 384.
// ---------------------------------------------------------------------------
#define K8_SMEM ((128*96 + 16*128) * 4)

__global__ void k8_gemm2(const float* g1, const float* b1)
{
    extern __shared__ float sm8[];
    float* sWt = sm8;               // [128][96]
    float* sa  = sm8 + 128*96;      // [16][128]
    __shared__ float sScale[128], sShift[128];

    int t = threadIdx.x;
    int hp = blockIdx.y, b = blockIdx.z;
    int W0 = blockIdx.x * 16;

    if (t < 128) {
        float n = 12000.f;
        float mean = P_SUM1[t] / n;
        float var  = P_SUMSQ1[t] / n - mean*mean;
        float sc = g1[t] * rsqrtf(var + 1e-5f);
        sScale[t] = sc;
        sShift[t] = b1[t] - mean*sc;
    }
    for (int idx = t; idx < 3072; idx += 384)
        ((float4*)sWt)[idx] = ((const float4*)d_Wcat2)[idx];
    __syncthreads();

    for (int idx = t; idx < 2048; idx += 384) {
        int ps = idx >> 7, i = idx & 127;
        int wp = W0 + ps;
        float v = 0.f;
        if (wp >= 2 && wp < 752) {
            float raw = d_o1raw[(((b*2 + hp)*750) + (wp-2))*128 + i];
            v = fmaxf(fmaf(raw, sScale[i], sShift[i]), 0.f);
        }
        sa[ps*128 + i] = v;
    }
    __syncthreads();

    int grp = t / 96, o = t - grp*96;
    for (int ps = grp; ps < 16; ps += 4) {
        int wp = W0 + ps;
        if (wp >= 754) continue;
        const float* av = sa + ps*128;
        float acc = 0.f;
        #pragma unroll 8
        for (int c = 0; c < 128; c++) acc += av[c] * sWt[c*96 + o];
        d_qkv2[(((b*2 + hp)*754) + wp)*96 + o] = acc;
    }
}

// ---------------------------------------------------------------------------
// K9: stage2 attention combine + in-block emb2, warp per position.
// grid (188, 2), block 128.
// ---------------------------------------------------------------------------
__global__ void k9_attn2(const float* p2_em, const float* p2_ea, const float* p2_eb)
{
    __shared__ float sla9[8], slb9[20], semb[40];
    int tid = threadIdx.x;
    if (tid < 28) {
        float acc = 0.f;
        if (tid < 8) {
            int m = tid >> 1, i = tid & 1;
            for (int o = 0; o < 16; o++) acc += p2_em[m*16+o] * p2_ea[o*2+i];
            sla9[tid] = acc;
        } else {
            int dd = tid - 8;
            int m = dd / 5, j = dd % 5;
            for (int o = 0; o < 16; o++) acc += p2_em[m*16+o] * p2_eb[o*5+j];
            slb9[dd] = acc;
        }
    }
    __syncthreads();
    if (tid < 10) {
        int kl = tid, i = kl / 5, j = kl % 5;
        float lg[4];
        #pragma unroll
        for (int m = 0; m < 4; m++) lg[m] = sla9[m*2+i] + slb9[m*5+j];
        float mx = fmaxf(fmaxf(lg[0],lg[1]), fmaxf(lg[2],lg[3]));
        float e[4], s = 0.f;
        #pragma unroll
        for (int m = 0; m < 4; m++) { e[m] = __expf(lg[m]-mx); s += e[m]; }
        #pragma unroll
        for (int m = 0; m < 4; m++) semb[kl*4+m] = e[m] / s;
    }
    __syncthreads();

    int lane = tid & 31, wrp = tid >> 5;
    int w = blockIdx.x * 4 + wrp, b = blockIdx.y;
    if (w >= 750) return;

    const float* base = d_qkv2 + (size_t)b * 2 * 754 * 96;
    const float* qp = base + (w + 2) * 96;
    float qv = (lane < 16) ? qp[lane] : 0.f;

    float scl[10];
    float mx = -1e30f;
    #pragma unroll
    for (int kl = 0; kl < 10; kl++) {
        int i = kl / 5, j = kl % 5;
        const float* kp = base + (i*754 + (w+j))*96 + 16;
        float pr = (lane < 16) ? qv * kp[lane] : 0.f;
        #pragma unroll
        for (int off = 8; off; off >>= 1) pr += __shfl_xor_sync(0xffffffffu, pr, off);
        scl[kl] = pr;
        mx = fmaxf(mx, pr);
    }
    float s = 0.f;
    #pragma unroll
    for (int kl = 0; kl < 10; kl++) { scl[kl] = __expf(scl[kl]-mx); s += scl[kl]; }
    float inv = 1.f / s;
    if (lane < 16) {
        float acc = 0.f;
        #pragma unroll
        for (int kl = 0; kl < 10; kl++) {
            int i = kl / 5, j = kl % 5;
            float4 v = *(const float4*)(base + (i*754 + (w+j))*96 + 32 + lane*4);
            float aw = scl[kl] * inv;
            acc += aw * (semb[kl*4]*v.x + semb[kl*4+1]*v.y + semb[kl*4+2]*v.z + semb[kl*4+3]*v.w);
        }
        d_out2[(b*750 + w)*16 + lane] = acc;
        atomicAdd(&P_SUM2[lane], acc);
        atomicAdd(&P_SUMSQ2[lane], acc*acc);
    }
}

// ---------------------------------------------------------------------------
// K11: stage2 BN + ReLU + AvgPool(1,56) -> out. grid (13,16,2), block 64
// ---------------------------------------------------------------------------
__global__ void k11_final(float* out, const float* g2, const float* b2)
{
    int n = blockIdx.x, c = blockIdx.y, b = blockIdx.z;
    int t = threadIdx.x;
    float nn = 1500.f;
    float mean = P_SUM2[c] / nn;
    float var  = P_SUMSQ2[c] / nn - mean*mean;
    float sc = g2[c] * rsqrtf(var + 1e-5f);
    float sf = b2[c] - mean * sc;

    float v = 0.f;
    if (t < 56) {
        float raw = d_out2[(b*750 + n*56 + t)*16 + c];
        v = fmaxf(fmaf(raw, sc, sf), 0.f);
    }
    __shared__ float shm[64];
    shm[t] = v;
    __syncthreads();
    for (int st = 32; st; st >>= 1) {
        if (t < st) shm[t] += shm[t+st];
        __syncthreads();
    }
    if (t == 0) out[(b*16 + c)*13 + n] = shm[0] * (1.f/56.f);
}

// ---------------------------------------------------------------------------
extern "C" void kernel_launch(void* const* d_in, const int* in_sizes, int n_in,
                              void* d_out, int out_size)
{
    const float* x     = (const float*)d_in[0];
    const float* p0_q  = (const float*)d_in[1];
    const float* p0_k  = (const float*)d_in[2];
    const float* p0_v  = (const float*)d_in[3];
    const float* p0_ea = (const float*)d_in[4];
    const float* p0_eb = (const float*)d_in[5];
    const float* p0_em = (const float*)d_in[6];
    const float* p0_g  = (const float*)d_in[7];
    const float* p0_b  = (const float*)d_in[8];
    const float* p1_q  = (const float*)d_in[9];
    const float* p1_k  = (const float*)d_in[10];
    const float* p1_v  = (const float*)d_in[11];
    const float* p1_ea = (const float*)d_in[12];
    const float* p1_eb = (const float*)d_in[13];
    const float* p1_em = (const float*)d_in[14];
    const float* p1_g  = (const float*)d_in[15];
    const float* p1_b  = (const float*)d_in[16];
    const float* p2_q  = (const float*)d_in[17];
    const float* p2_k  = (const float*)d_in[18];
    const float* p2_v  = (const float*)d_in[19];
    const float* p2_ea = (const float*)d_in[20];
    const float* p2_eb = (const float*)d_in[21];
    const float* p2_em = (const float*)d_in[22];
    const float* p2_g  = (const float*)d_in[23];
    const float* p2_b  = (const float*)d_in[24];
    float* out = (float*)d_out;

    static int smem_set = 0;
    if (!smem_set) {
        cudaFuncSetAttribute(k4_gemm1, cudaFuncAttributeMaxDynamicSharedMemorySize, K4_SMEM);
        cudaFuncSetAttribute(k5_attn1, cudaFuncAttributeMaxDynamicSharedMemorySize, K5_SMEM);
        cudaFuncSetAttribute(k8_gemm2, cudaFuncAttributeMaxDynamicSharedMemorySize, K8_SMEM);
        smem_set = 1;
    }

    k1_mega<<<64, 256>>>(x, p0_q, p0_k, p1_q, p1_k, p1_v, p2_q, p2_k, p2_v);
    k4_gemm1<<<dim3(94, 12), 256, K4_SMEM>>>(p0_v, p0_ea, p0_eb, p0_em, p0_g, p0_b);
    k5_attn1<<<dim3(150, 4, 2), 512, K5_SMEM>>>(p1_em, p1_ea, p1_eb);
    k8_gemm2<<<dim3(48, 2, 2), 384, K8_SMEM>>>(p1_g, p1_b);
    k9_attn2<<<dim3(188, 2), 128>>>(p2_em, p2_ea, p2_eb);
    k11_final<<<dim3(13, 16, 2), 64>>>(out, p2_g, p2_b);
}

// round 9
// speedup vs baseline: 1.0747x; 1.0747x over previous
#include <cuda_runtime.h>
#include <cuda_bf16.h>
#include <math.h>
#include <stdint.h>

// ---------------------------------------------------------------------------
// Static device scratch
// ---------------------------------------------------------------------------
__device__ float d_g0[5*12000];
__device__ __nv_bfloat16 d_h1h[12000*64];
__device__ __nv_bfloat16 d_h1l[12000*64];
__device__ float d_qkv1[2*6*1504*768];          // v cols = 256+o*4+m
__device__ float d_o1raw[2*2*750*128];
__device__ float d_qkv2[2*2*754*96];            // v cols = 32+o*4+m
__device__ float d_out2[2*750*16];

__device__ __nv_bfloat16 d_W1bh[768*64];
__device__ __nv_bfloat16 d_W1bl[768*64];
__device__ float d_Wcat2[128*96];
__device__ float d_Weff0[5*64];
__device__ float d_emb1[4*10];
__device__ float d_emb2[4*10];
__device__ float d_C0;

// contiguous stats block, zeroed by k0 block 16:
// [0,30)=S0, [30,158)=sum1, [158,286)=sumsq1, [286,302)=sum2, [302,318)=sumsq2
__device__ float d_stats[318];
#define P_S0     (d_stats)
#define P_SUM1   (d_stats + 30)
#define P_SUMSQ1 (d_stats + 158)
#define P_SUM2   (d_stats + 286)
#define P_SUMSQ2 (d_stats + 302)

__device__ __forceinline__ void mma_bf16(float4& c,
    uint32_t a0, uint32_t a1, uint32_t a2, uint32_t a3,
    uint32_t b0, uint32_t b1)
{
    asm volatile(
        "mma.sync.aligned.m16n8k16.row.col.f32.bf16.bf16.f32 "
        "{%0,%1,%2,%3},{%4,%5,%6,%7},{%8,%9},{%0,%1,%2,%3};"
        : "+f"(c.x), "+f"(c.y), "+f"(c.z), "+f"(c.w)
        : "r"(a0), "r"(a1), "r"(a2), "r"(a3), "r"(b0), "r"(b1));
}

__device__ __forceinline__ void ldsm_x4(uint32_t& r0, uint32_t& r1, uint32_t& r2, uint32_t& r3,
                                        uint32_t addr)
{
    asm volatile("ldmatrix.sync.aligned.m8n8.x4.shared.b16 {%0,%1,%2,%3}, [%4];"
        : "=r"(r0), "=r"(r1), "=r"(r2), "=r"(r3) : "r"(addr));
}

// ---------------------------------------------------------------------------
// K0: grid 17 blocks. Blocks 0..15: weight conversion. Block 16: embeddings,
//     Weff0, C0, stats zeroing.
// ---------------------------------------------------------------------------
__global__ void k0_pre(const float* p0_q, const float* p0_k, const float* p0_v,
                       const float* p0_ea, const float* p0_eb, const float* p0_em,
                       const float* p1_q, const float* p1_k, const float* p1_v,
                       const float* p1_ea, const float* p1_eb, const float* p1_em,
                       const float* p2_q, const float* p2_k, const float* p2_v,
                       const float* p2_ea, const float* p2_eb, const float* p2_em)
{
    int t = threadIdx.x;
    int blk = blockIdx.x;

    if (blk < 16) {
        #pragma unroll
        for (int u = 0; u < 12; u++) {
            int idx = blk*3072 + u*256 + t;
            int j = idx / 64, c = idx % 64;
            float v;
            if (j < 128)       v = p1_q[c*128 + j];
            else if (j < 256)  v = p1_k[c*128 + (j-128)];
            else { int o = (j-256) >> 2, m = (j-256) & 3; v = p1_v[(m*64+c)*128 + o]; }
            __nv_bfloat16 hi = __float2bfloat16_rn(v);
            d_W1bh[idx] = hi;
            d_W1bl[idx] = __float2bfloat16_rn(v - __bfloat162float(hi));
        }
        #pragma unroll
        for (int u = 0; u < 3; u++) {
            int idx = blk*768 + u*256 + t;
            int c = idx / 96, j = idx % 96;
            float v;
            if (j < 16)       v = p2_q[c*16 + j];
            else if (j < 32)  v = p2_k[c*16 + (j-16)];
            else { int o = (j-32) >> 2, m = (j-32) & 3; v = p2_v[(m*128+c)*16 + o]; }
            d_Wcat2[idx] = v;
        }
        return;
    }

    // blk == 16: zero stats + small precomputes
    for (int i = t; i < 318; i += 256) d_stats[i] = 0.f;

    __shared__ float logit0[4][5], logit1[4][10], logit2[4][10];
    __shared__ float emb0s[4][5];

    if (t == 0) {
        float s = 0.f;
        for (int o = 0; o < 64; o++) s += p0_q[o] * p0_k[o];
        d_C0 = s;
    }
    if (t >= 128 && t < 148) {
        int u = t - 128; int m = u / 5, j = u % 5;
        float la = 0.f, lb = 0.f;
        for (int o = 0; o < 64; o++) {
            la += p0_em[m*64+o] * p0_ea[o];
            lb += p0_em[m*64+o] * p0_eb[o*5+j];
        }
        logit0[m][j] = la + lb;
    }
    if (t < 40) {
        int m = t / 10, kl = t % 10, i = kl / 5, j = kl % 5;
        float la = 0.f, lb = 0.f;
        for (int o = 0; o < 128; o++) {
            la += p1_em[m*128+o] * p1_ea[o*2+i];
            lb += p1_em[m*128+o] * p1_eb[o*5+j];
        }
        logit1[m][kl] = la + lb;
    }
    if (t >= 64 && t < 104) {
        int u = t - 64; int m = u / 10, kl = u % 10, i = kl / 5, j = kl % 5;
        float la = 0.f, lb = 0.f;
        for (int o = 0; o < 16; o++) {
            la += p2_em[m*16+o] * p2_ea[o*2+i];
            lb += p2_em[m*16+o] * p2_eb[o*5+j];
        }
        logit2[m][kl] = la + lb;
    }
    __syncthreads();
    if (t < 5) {
        float mx = -1e30f;
        for (int m = 0; m < 4; m++) mx = fmaxf(mx, logit0[m][t]);
        float e[4], s = 0.f;
        for (int m = 0; m < 4; m++) { e[m] = __expf(logit0[m][t]-mx); s += e[m]; }
        for (int m = 0; m < 4; m++) emb0s[m][t] = e[m] / s;
    }
    if (t >= 32 && t < 42) {
        int kl = t - 32;
        float mx = -1e30f;
        for (int m = 0; m < 4; m++) mx = fmaxf(mx, logit1[m][kl]);
        float e[4], s = 0.f;
        for (int m = 0; m < 4; m++) { e[m] = __expf(logit1[m][kl]-mx); s += e[m]; }
        for (int m = 0; m < 4; m++) d_emb1[m*10+kl] = e[m] / s;
    }
    if (t >= 64 && t < 74) {
        int kl = t - 64;
        float mx = -1e30f;
        for (int m = 0; m < 4; m++) mx = fmaxf(mx, logit2[m][kl]);
        float e[4], s = 0.f;
        for (int m = 0; m < 4; m++) { e[m] = __expf(logit2[m][kl]-mx); s += e[m]; }
        for (int m = 0; m < 4; m++) d_emb2[m*10+kl] = e[m] / s;
    }
    __syncthreads();
    for (int idx = t; idx < 5*64; idx += blockDim.x) {
        int l = idx / 64, o = idx % 64;
        float s = 0.f;
        for (int m = 0; m < 4; m++) s += emb0s[m][l] * p0_v[m*64+o];
        d_Weff0[idx] = s;
    }
}

// ---------------------------------------------------------------------------
// K1: stage0 attention -> g[5] + low-rank BN stats. grid (24,8,2), block 128
// ---------------------------------------------------------------------------
__global__ void k1_stem0(const float* x)
{
    int tid = threadIdx.x;
    int w = blockIdx.x * 128 + tid;
    int h = blockIdx.y, b = blockIdx.z;
    bool valid = (w < 3000);

    float g[5] = {0.f,0.f,0.f,0.f,0.f};
    if (valid) {
        const float* xr = x + (b*8 + h) * 3000;
        float xc = xr[w];
        float C0 = d_C0;
        float xl[5], sc[5];
        float mx = -1e30f;
        #pragma unroll
        for (int l = 0; l < 5; l++) {
            int c = w + l - 2;
            xl[l] = (c >= 0 && c < 3000) ? xr[c] : 0.f;
            sc[l] = xc * xl[l] * C0;
            mx = fmaxf(mx, sc[l]);
        }
        float s = 0.f;
        #pragma unroll
        for (int l = 0; l < 5; l++) { sc[l] = __expf(sc[l]-mx); s += sc[l]; }
        float inv = 1.f / s;
        #pragma unroll
        for (int l = 0; l < 5; l++) g[l] = sc[l] * inv * xl[l];
    }

    float st[20];
    {
        int si = 0;
        #pragma unroll
        for (int l = 0; l < 5; l++) st[si++] = g[l];
        #pragma unroll
        for (int l = 0; l < 5; l++)
            #pragma unroll
            for (int l2 = l; l2 < 5; l2++) st[si++] = g[l]*g[l2];
    }
    #pragma unroll
    for (int i = 0; i < 20; i++)
        #pragma unroll
        for (int off = 16; off; off >>= 1)
            st[i] += __shfl_xor_sync(0xffffffffu, st[i], off);

    __shared__ float red[4][20];
    int lane = tid & 31, wrp = tid >> 5;
    if (lane == 0)
        for (int i = 0; i < 20; i++) red[wrp][i] = st[i];
    __syncthreads();
    if (tid < 20) {
        float v = red[0][tid] + red[1][tid] + red[2][tid] + red[3][tid];
        int slot;
        if (tid < 5) slot = tid;
        else {
            int k = tid - 5, l = 0;
            while (k >= 5 - l) { k -= 5 - l; l++; }
            slot = 5 + l*5 + (l + k);
        }
        atomicAdd(&P_S0[slot], v);
    }

    if (valid && !(h & 1) && !(w & 1)) {
        int p = b*6000 + (h>>1)*1500 + (w>>1);
        #pragma unroll
        for (int l = 0; l < 5; l++) d_g0[l*12000 + p] = g[l];
    }
}

// ---------------------------------------------------------------------------
// K3: stage0 BN + ReLU -> h1 bf16 hi/lo. grid 3000, block 256
// ---------------------------------------------------------------------------
__global__ void k3_h1(const float* g0, const float* b0)
{
    __shared__ float sW[5*64];
    __shared__ float sScale[64], sShift[64];
    int tid = threadIdx.x;
    for (int i = tid; i < 320; i += 256) sW[i] = d_Weff0[i];
    __syncthreads();
    if (tid < 64) {
        int c = tid;
        float Wc[5];
        #pragma unroll
        for (int l = 0; l < 5; l++) Wc[l] = sW[l*64 + c];
        float mn = 0.f, mq = 0.f;
        #pragma unroll
        for (int l = 0; l < 5; l++) {
            mn += P_S0[l] * Wc[l];
            #pragma unroll
            for (int l2 = 0; l2 < 5; l2++) {
                int lo = l < l2 ? l : l2, hi = l < l2 ? l2 : l;
                mq += P_S0[5 + lo*5 + hi] * Wc[l] * Wc[l2];
            }
        }
        float n = 48000.f;
        float mean = mn / n;
        float var  = mq / n - mean*mean;
        float sc = g0[c] * rsqrtf(var + 1e-5f);
        sScale[c] = sc;
        sShift[c] = b0[c] - mean * sc;
    }
    __syncthreads();

    int c = tid & 63;
    int p = blockIdx.x * 4 + (tid >> 6);
    float a = 0.f;
    #pragma unroll
    for (int l = 0; l < 5; l++) a += d_g0[l*12000 + p] * sW[l*64 + c];
    float y = fmaxf(fmaf(a, sScale[c], sShift[c]), 0.f);
    __nv_bfloat16 hi = __float2bfloat16_rn(y);
    d_h1h[p*64 + c] = hi;
    d_h1l[p*64 + c] = __float2bfloat16_rn(y - __bfloat162float(hi));
}

// ---------------------------------------------------------------------------
// K4: stage1 qkv GEMM (real rows only, M'=12032), bf16 3-term + ldmatrix,
// 4x2 warp layout. Zero-fills hp=0 pad rows. grid (94, 12), block 256.
// ---------------------------------------------------------------------------
#define K4_SMEM ((128*72 + 128*72 + 64*72 + 64*72) * 2)

__global__ void k4_gemm1()
{
    extern __shared__ __nv_bfloat16 sh[];
    __nv_bfloat16* Ah = sh;
    __nv_bfloat16* Al = Ah + 128*72;
    __nv_bfloat16* Bh = Al + 128*72;
    __nv_bfloat16* Bl = Bh + 64*72;

    int tid = threadIdx.x;
    int rowBase = blockIdx.x * 128;
    int colBase = blockIdx.y * 64;

    {
        int blockId = blockIdx.y * 94 + blockIdx.x;
        float4 z4 = make_float4(0.f,0.f,0.f,0.f);
        #pragma unroll
        for (int u = 0; u < 2; u++) {
            int f4idx = blockId*512 + u*256 + tid;
            int fidx = f4idx * 4;
            int row = fidx / 768, col = fidx % 768;
            int b = row >= 1504;
            int wp = row - b*1504;
            *(float4*)&d_qkv1[((size_t)b*9024 + wp)*768 + col] = z4;
        }
    }

    {
        int r = tid >> 1;
        int half = (tid & 1) * 32;
        int prow = rowBase + r;
        int b = prow / 6016; int rem = prow % 6016;
        int hp = 1 + rem / 1504; int wp = rem % 1504;
        bool valid = (wp >= 2 && wp < 1502);
        __nv_bfloat16* dh = Ah + r*72 + half;
        __nv_bfloat16* dl = Al + r*72 + half;
        if (valid) {
            int pos = ((b*4 + (hp-1))*1500 + (wp-2))*64 + half;
            const uint4* sH = (const uint4*)(d_h1h + pos);
            const uint4* sL = (const uint4*)(d_h1l + pos);
            #pragma unroll
            for (int u = 0; u < 4; u++) {
                ((uint4*)dh)[u] = sH[u];
                ((uint4*)dl)[u] = sL[u];
            }
        } else {
            uint4 z = make_uint4(0,0,0,0);
            #pragma unroll
            for (int u = 0; u < 4; u++) { ((uint4*)dh)[u] = z; ((uint4*)dl)[u] = z; }
        }
    }
    {
        int n = tid >> 2;
        int seg = (tid & 3) * 16;
        const uint4* sH = (const uint4*)(d_W1bh + (colBase + n)*64 + seg);
        const uint4* sL = (const uint4*)(d_W1bl + (colBase + n)*64 + seg);
        uint4* dh = (uint4*)(Bh + n*72 + seg);
        uint4* dl = (uint4*)(Bl + n*72 + seg);
        dh[0] = sH[0]; dh[1] = sH[1];
        dl[0] = sL[0]; dl[1] = sL[1];
    }
    __syncthreads();

    int lane = tid & 31, wid = tid >> 5;
    int g = lane >> 2, tg = lane & 3;
    int mr   = (wid >> 1) * 32;
    int ncol = (wid & 1) * 32;

    int arow = (lane < 16) ? lane : (lane - 16);
    int acol = (lane < 16) ? 0 : 8;
    uint32_t aAddrH[2], aAddrL[2];
    #pragma unroll
    for (int mt = 0; mt < 2; mt++) {
        aAddrH[mt] = (uint32_t)__cvta_generic_to_shared(Ah + (mr + mt*16 + arow)*72 + acol);
        aAddrL[mt] = (uint32_t)__cvta_generic_to_shared(Al + (mr + mt*16 + arow)*72 + acol);
    }
    int brow = (lane & 7) + ((lane >> 4) << 3);
    int bcol = ((lane >> 3) & 1) * 8;
    uint32_t bAddrH[2], bAddrL[2];
    #pragma unroll
    for (int pr = 0; pr < 2; pr++) {
        bAddrH[pr] = (uint32_t)__cvta_generic_to_shared(Bh + (ncol + pr*16 + brow)*72 + bcol);
        bAddrL[pr] = (uint32_t)__cvta_generic_to_shared(Bl + (ncol + pr*16 + brow)*72 + bcol);
    }

    float4 acc[2][4];
    #pragma unroll
    for (int i = 0; i < 2; i++)
        #pragma unroll
        for (int j = 0; j < 4; j++) acc[i][j] = make_float4(0.f,0.f,0.f,0.f);

    #pragma unroll
    for (int ks = 0; ks < 4; ks++) {
        uint32_t koff = ks * 32;
        uint32_t ah[2][4], al[2][4], bh[2][4], bl[2][4];
        #pragma unroll
        for (int mt = 0; mt < 2; mt++) {
            ldsm_x4(ah[mt][0],ah[mt][1],ah[mt][2],ah[mt][3], aAddrH[mt] + koff);
            ldsm_x4(al[mt][0],al[mt][1],al[mt][2],al[mt][3], aAddrL[mt] + koff);
        }
        #pragma unroll
        for (int pr = 0; pr < 2; pr++) {
            ldsm_x4(bh[pr][0],bh[pr][1],bh[pr][2],bh[pr][3], bAddrH[pr] + koff);
            ldsm_x4(bl[pr][0],bl[pr][1],bl[pr][2],bl[pr][3], bAddrL[pr] + koff);
        }
        #pragma unroll
        for (int mt = 0; mt < 2; mt++)
            #pragma unroll
            for (int pr = 0; pr < 2; pr++) {
                mma_bf16(acc[mt][2*pr  ], ah[mt][0],ah[mt][1],ah[mt][2],ah[mt][3], bh[pr][0],bh[pr][1]);
                mma_bf16(acc[mt][2*pr  ], ah[mt][0],ah[mt][1],ah[mt][2],ah[mt][3], bl[pr][0],bl[pr][1]);
                mma_bf16(acc[mt][2*pr  ], al[mt][0],al[mt][1],al[mt][2],al[mt][3], bh[pr][0],bh[pr][1]);
                mma_bf16(acc[mt][2*pr+1], ah[mt][0],ah[mt][1],ah[mt][2],ah[mt][3], bh[pr][2],bh[pr][3]);
                mma_bf16(acc[mt][2*pr+1], ah[mt][0],ah[mt][1],ah[mt][2],ah[mt][3], bl[pr][2],bl[pr][3]);
                mma_bf16(acc[mt][2*pr+1], al[mt][0],al[mt][1],al[mt][2],al[mt][3], bh[pr][2],bh[pr][3]);
            }
    }

    #pragma unroll
    for (int mt = 0; mt < 2; mt++) {
        #pragma unroll
        for (int half = 0; half < 2; half++) {
            int prow = rowBase + mr + mt*16 + half*8 + g;
            int b = prow / 6016; int rem = prow % 6016;
            int hp = 1 + rem / 1504; int wp = rem % 1504;
            size_t orow = (size_t)(b*6 + hp)*1504 + wp;
            #pragma unroll
            for (int j = 0; j < 4; j++) {
                int col = colBase + ncol + j*8 + tg*2;
                float2 v = half ? make_float2(acc[mt][j].z, acc[mt][j].w)
                                : make_float2(acc[mt][j].x, acc[mt][j].y);
                *(float2*)&d_qkv1[orow*768 + col] = v;
            }
        }
    }
}

// ---------------------------------------------------------------------------
// K5: stage1 attention combine, smem-staged kv window.
// 10 positions/block, 512 threads. grid (150, 4, 2).
// ---------------------------------------------------------------------------
#define K5_SMEM ((10*128 + 28*640) * 4)

__global__ void k5_attn1()
{
    extern __shared__ float sm5[];
    float* sq = sm5;                // [10][128]
    float* kv = sm5 + 10*128;       // [28][640]

    int w0 = blockIdx.x * 10, h = blockIdx.y, b = blockIdx.z;
    int tid = threadIdx.x, lane = tid & 31, wrp = tid >> 5;  // 16 warps
    __shared__ float ssc[10][10];
    __shared__ float cm4[10][40];

    const float* base = d_qkv1 + (size_t)b * 6 * 1504 * 768;

    for (int idx = tid; idx < 320; idx += 512) {
        int p = idx >> 5, c4 = idx & 31;
        ((float4*)sq)[p*32 + c4] =
            *(const float4*)(base + ((h+1)*1504 + (w0+2+p))*768 + c4*4);
    }
    for (int idx = tid; idx < 4480; idx += 512) {
        int r = idx / 160, c4 = idx % 160;
        int i = r / 14, jj = r % 14;
        ((float4*)(kv + r*640))[c4] =
            *(const float4*)(base + ((h+i)*1504 + (w0+jj))*768 + 128 + c4*4);
    }
    __syncthreads();

    for (int pair = wrp; pair < 100; pair += 16) {
        int p = pair / 10, kl = pair % 10;
        int i = kl / 5, j = kl % 5;
        float4 q4 = ((const float4*)(sq + p*128))[lane];
        float4 k4 = ((const float4*)(kv + (i*14 + p + j)*640))[lane];
        float s = q4.x*k4.x + q4.y*k4.y + q4.z*k4.z + q4.w*k4.w;
        #pragma unroll
        for (int off = 16; off; off >>= 1) s += __shfl_xor_sync(0xffffffffu, s, off);
        if (lane == 0) ssc[p][kl] = s;
    }
    __syncthreads();
    if (tid < 10) {
        float mx = -1e30f;
        #pragma unroll
        for (int kl = 0; kl < 10; kl++) mx = fmaxf(mx, ssc[tid][kl]);
        float e[10], s = 0.f;
        #pragma unroll
        for (int kl = 0; kl < 10; kl++) { e[kl] = __expf(ssc[tid][kl]-mx); s += e[kl]; }
        float inv = 1.f / s;
        #pragma unroll
        for (int kl = 0; kl < 10; kl++) {
            float a = e[kl] * inv;
            #pragma unroll
            for (int m = 0; m < 4; m++) cm4[tid][kl*4+m] = a * d_emb1[m*10+kl];
        }
    }
    __syncthreads();

    int o = tid & 127;
    int ph = tid >> 7;
    float s1 = 0.f, s2 = 0.f;
    for (int p = ph; p < 10; p += 4) {
        const float* cw = cm4[p];
        float acc = 0.f;
        #pragma unroll
        for (int kl = 0; kl < 10; kl++) {
            int i = kl / 5, j = kl % 5;
            float4 v = *(const float4*)(kv + (i*14 + p + j)*640 + 128 + o*4);
            acc += cw[kl*4]*v.x + cw[kl*4+1]*v.y + cw[kl*4+2]*v.z + cw[kl*4+3]*v.w;
        }
        s1 += acc; s2 += acc*acc;
        if (!(h & 1) && !((w0+p) & 1))
            d_o1raw[((b*2 + (h>>1))*750 + ((w0+p)>>1))*128 + o] = acc;
    }
    atomicAdd(&P_SUM1[o], s1);
    atomicAdd(&P_SUMSQ1[o], s2);
}

// ---------------------------------------------------------------------------
// K8: stage2 qkv GEMM, ILP-split dots, 8 positions/block.
// grid (95, 2, 2), block 256. Each thread: 3 (pos,out) pairs,
// each a 128-dot with 4 independent accumulators.
// ---------------------------------------------------------------------------
#define K8_SMEM ((128*96 + 8*128) * 4)

__global__ void k8_gemm2(const float* g1, const float* b1)
{
    extern __shared__ float sm8[];
    float* sWt = sm8;               // [128][96]
    float* sa  = sm8 + 128*96;      // [8][128]
    __shared__ float sScale[128], sShift[128];

    int t = threadIdx.x;
    int hp = blockIdx.y, b = blockIdx.z;
    int W0 = blockIdx.x * 8;

    if (t < 128) {
        float n = 12000.f;
        float mean = P_SUM1[t] / n;
        float var  = P_SUMSQ1[t] / n - mean*mean;
        float sc = g1[t] * rsqrtf(var + 1e-5f);
        sScale[t] = sc;
        sShift[t] = b1[t] - mean*sc;
    }
    // stage weights: 3072 float4 / 256 threads = 12 each
    for (int idx = t; idx < 3072; idx += 256)
        ((float4*)sWt)[idx] = ((const float4*)d_Wcat2)[idx];
    __syncthreads();

    // stage activations with BN+ReLU: 1024 floats
    for (int idx = t; idx < 1024; idx += 256) {
        int ps = idx >> 7, i = idx & 127;
        int wp = W0 + ps;
        float v = 0.f;
        if (wp >= 2 && wp < 752) {
            float raw = d_o1raw[(((b*2 + hp)*750) + (wp-2))*128 + i];
            v = fmaxf(fmaf(raw, sScale[i], sShift[i]), 0.f);
        }
        sa[ps*128 + i] = v;
    }
    __syncthreads();

    // 768 (ps,o) pairs over 256 threads = 3 each; 4-way acc split
    #pragma unroll
    for (int k = 0; k < 3; k++) {
        int pair = t + k*256;
        int ps = pair / 96, o = pair - (pair/96)*96;
        int wp = W0 + ps;
        if (wp >= 754) continue;
        const float* av = sa + ps*128;
        float a0 = 0.f, a1 = 0.f, a2 = 0.f, a3 = 0.f;
        #pragma unroll
        for (int c = 0; c < 32; c++) {
            a0 = fmaf(av[c],     sWt[c*96 + o],        a0);
            a1 = fmaf(av[c+32],  sWt[(c+32)*96 + o],   a1);
            a2 = fmaf(av[c+64],  sWt[(c+64)*96 + o],   a2);
            a3 = fmaf(av[c+96],  sWt[(c+96)*96 + o],   a3);
        }
        d_qkv2[(((b*2 + hp)*754) + wp)*96 + o] = (a0 + a1) + (a2 + a3);
    }
}

// ---------------------------------------------------------------------------
// K9: stage2 attention combine, warp per position. grid (188, 2), block 128
// ---------------------------------------------------------------------------
__global__ void k9_attn2()
{
    __shared__ float semb[40];
    int tid = threadIdx.x;
    if (tid < 40) { int kl = tid >> 2, m = tid & 3; semb[tid] = d_emb2[m*10+kl]; }
    __syncthreads();

    int lane = tid & 31, wrp = tid >> 5;
    int w = blockIdx.x * 4 + wrp, b = blockIdx.y;
    if (w >= 750) return;

    const float* base = d_qkv2 + (size_t)b * 2 * 754 * 96;
    const float* qp = base + (w + 2) * 96;
    float qv = (lane < 16) ? qp[lane] : 0.f;

    float scl[10];
    float mx = -1e30f;
    #pragma unroll
    for (int kl = 0; kl < 10; kl++) {
        int i = kl / 5, j = kl % 5;
        const float* kp = base + (i*754 + (w+j))*96 + 16;
        float pr = (lane < 16) ? qv * kp[lane] : 0.f;
        #pragma unroll
        for (int off = 8; off; off >>= 1) pr += __shfl_xor_sync(0xffffffffu, pr, off);
        scl[kl] = pr;
        mx = fmaxf(mx, pr);
    }
    float s = 0.f;
    #pragma unroll
    for (int kl = 0; kl < 10; kl++) { scl[kl] = __expf(scl[kl]-mx); s += scl[kl]; }
    float inv = 1.f / s;
    if (lane < 16) {
        float acc = 0.f;
        #pragma unroll
        for (int kl = 0; kl < 10; kl++) {
            int i = kl / 5, j = kl % 5;
            float4 v = *(const float4*)(base + (i*754 + (w+j))*96 + 32 + lane*4);
            float aw = scl[kl] * inv;
            acc += aw * (semb[kl*4]*v.x + semb[kl*4+1]*v.y + semb[kl*4+2]*v.z + semb[kl*4+3]*v.w);
        }
        d_out2[(b*750 + w)*16 + lane] = acc;
        atomicAdd(&P_SUM2[lane], acc);
        atomicAdd(&P_SUMSQ2[lane], acc*acc);
    }
}

// ---------------------------------------------------------------------------
// K11: stage2 BN + ReLU + AvgPool(1,56) -> out. grid (13,16,2), block 64
// ---------------------------------------------------------------------------
__global__ void k11_final(float* out, const float* g2, const float* b2)
{
    int n = blockIdx.x, c = blockIdx.y, b = blockIdx.z;
    int t = threadIdx.x;
    float nn = 1500.f;
    float mean = P_SUM2[c] / nn;
    float var  = P_SUMSQ2[c] / nn - mean*mean;
    float sc = g2[c] * rsqrtf(var + 1e-5f);
    float sf = b2[c] - mean * sc;

    float v = 0.f;
    if (t < 56) {
        float raw = d_out2[(b*750 + n*56 + t)*16 + c];
        v = fmaxf(fmaf(raw, sc, sf), 0.f);
    }
    __shared__ float shm[64];
    shm[t] = v;
    __syncthreads();
    for (int st = 32; st; st >>= 1) {
        if (t < st) shm[t] += shm[t+st];
        __syncthreads();
    }
    if (t == 0) out[(b*16 + c)*13 + n] = shm[0] * (1.f/56.f);
}

// ---------------------------------------------------------------------------
extern "C" void kernel_launch(void* const* d_in, const int* in_sizes, int n_in,
                              void* d_out, int out_size)
{
    const float* x     = (const float*)d_in[0];
    const float* p0_q  = (const float*)d_in[1];
    const float* p0_k  = (const float*)d_in[2];
    const float* p0_v  = (const float*)d_in[3];
    const float* p0_ea = (const float*)d_in[4];
    const float* p0_eb = (const float*)d_in[5];
    const float* p0_em = (const float*)d_in[6];
    const float* p0_g  = (const float*)d_in[7];
    const float* p0_b  = (const float*)d_in[8];
    const float* p1_q  = (const float*)d_in[9];
    const float* p1_k  = (const float*)d_in[10];
    const float* p1_v  = (const float*)d_in[11];
    const float* p1_ea = (const float*)d_in[12];
    const float* p1_eb = (const float*)d_in[13];
    const float* p1_em = (const float*)d_in[14];
    const float* p1_g  = (const float*)d_in[15];
    const float* p1_b  = (const float*)d_in[16];
    const float* p2_q  = (const float*)d_in[17];
    const float* p2_k  = (const float*)d_in[18];
    const float* p2_v  = (const float*)d_in[19];
    const float* p2_ea = (const float*)d_in[20];
    const float* p2_eb = (const float*)d_in[21];
    const float* p2_em = (const float*)d_in[22];
    const float* p2_g  = (const float*)d_in[23];
    const float* p2_b  = (const float*)d_in[24];
    float* out = (float*)d_out;

    static int smem_set = 0;
    if (!smem_set) {
        cudaFuncSetAttribute(k4_gemm1, cudaFuncAttributeMaxDynamicSharedMemorySize, K4_SMEM);
        cudaFuncSetAttribute(k5_attn1, cudaFuncAttributeMaxDynamicSharedMemorySize, K5_SMEM);
        cudaFuncSetAttribute(k8_gemm2, cudaFuncAttributeMaxDynamicSharedMemorySize, K8_SMEM);
        smem_set = 1;
    }

    k0_pre<<<17, 256>>>(p0_q, p0_k, p0_v, p0_ea, p0_eb, p0_em,
                        p1_q, p1_k, p1_v, p1_ea, p1_eb, p1_em,
                        p2_q, p2_k, p2_v, p2_ea, p2_eb, p2_em);
    k1_stem0<<<dim3(24, 8, 2), 128>>>(x);
    k3_h1<<<3000, 256>>>(p0_g, p0_b);
    k4_gemm1<<<dim3(94, 12), 256, K4_SMEM>>>();
    k5_attn1<<<dim3(150, 4, 2), 512, K5_SMEM>>>();
    k8_gemm2<<<dim3(95, 2, 2), 256, K8_SMEM>>>(p1_g, p1_b);
    k9_attn2<<<dim3(188, 2), 128>>>();
    k11_final<<<dim3(13, 16, 2), 64>>>(out, p2_g, p2_b);
}

// round 11
// speedup vs baseline: 1.1178x; 1.0401x over previous
#include <cuda_runtime.h>
#include <cuda_bf16.h>
#include <cuda_fp16.h>
#include <math.h>
#include <stdint.h>

// ---------------------------------------------------------------------------
// Static device scratch
// ---------------------------------------------------------------------------
__device__ float d_g0[5*12000];
__device__ __nv_bfloat16 d_h1h[12000*64];
__device__ __nv_bfloat16 d_h1l[12000*64];
__device__ float d_qk1[2*6*1504*256];           // q cols 0..127, k cols 128..255 (fp32)
__device__ __half d_v1[2*6*1504*512];           // v cols (o*4+m) in fp16
__device__ float d_o1raw[2*2*750*128];
__device__ float d_qkv2[2*2*754*96];            // v cols = 32+o*4+m
__device__ float d_out2[2*750*16];

__device__ __nv_bfloat16 d_W1bh[768*64];
__device__ __nv_bfloat16 d_W1bl[768*64];
__device__ float d_Wcat2[128*96];
__device__ float d_Weff0[5*64];
__device__ float d_emb1[4*10];
__device__ float d_emb2[4*10];
__device__ float d_C0;

// contiguous stats block, zeroed by k0 block 16:
// [0,30)=S0, [30,158)=sum1, [158,286)=sumsq1, [286,302)=sum2, [302,318)=sumsq2
__device__ float d_stats[318];
#define P_S0     (d_stats)
#define P_SUM1   (d_stats + 30)
#define P_SUMSQ1 (d_stats + 158)
#define P_SUM2   (d_stats + 286)
#define P_SUMSQ2 (d_stats + 302)

__device__ __forceinline__ void mma_bf16(float4& c,
    uint32_t a0, uint32_t a1, uint32_t a2, uint32_t a3,
    uint32_t b0, uint32_t b1)
{
    asm volatile(
        "mma.sync.aligned.m16n8k16.row.col.f32.bf16.bf16.f32 "
        "{%0,%1,%2,%3},{%4,%5,%6,%7},{%8,%9},{%0,%1,%2,%3};"
        : "+f"(c.x), "+f"(c.y), "+f"(c.z), "+f"(c.w)
        : "r"(a0), "r"(a1), "r"(a2), "r"(a3), "r"(b0), "r"(b1));
}

__device__ __forceinline__ void ldsm_x4(uint32_t& r0, uint32_t& r1, uint32_t& r2, uint32_t& r3,
                                        uint32_t addr)
{
    asm volatile("ldmatrix.sync.aligned.m8n8.x4.shared.b16 {%0,%1,%2,%3}, [%4];"
        : "=r"(r0), "=r"(r1), "=r"(r2), "=r"(r3) : "r"(addr));
}

// ---------------------------------------------------------------------------
// K0: grid 17 blocks. Blocks 0..15: weight conversion. Block 16: embeddings,
//     Weff0, C0, stats zeroing.
// ---------------------------------------------------------------------------
__global__ void k0_pre(const float* p0_q, const float* p0_k, const float* p0_v,
                       const float* p0_ea, const float* p0_eb, const float* p0_em,
                       const float* p1_q, const float* p1_k, const float* p1_v,
                       const float* p1_ea, const float* p1_eb, const float* p1_em,
                       const float* p2_q, const float* p2_k, const float* p2_v,
                       const float* p2_ea, const float* p2_eb, const float* p2_em)
{
    int t = threadIdx.x;
    int blk = blockIdx.x;

    if (blk < 16) {
        #pragma unroll
        for (int u = 0; u < 12; u++) {
            int idx = blk*3072 + u*256 + t;
            int j = idx / 64, c = idx % 64;
            float v;
            if (j < 128)       v = p1_q[c*128 + j];
            else if (j < 256)  v = p1_k[c*128 + (j-128)];
            else { int o = (j-256) >> 2, m = (j-256) & 3; v = p1_v[(m*64+c)*128 + o]; }
            __nv_bfloat16 hi = __float2bfloat16_rn(v);
            d_W1bh[idx] = hi;
            d_W1bl[idx] = __float2bfloat16_rn(v - __bfloat162float(hi));
        }
        #pragma unroll
        for (int u = 0; u < 3; u++) {
            int idx = blk*768 + u*256 + t;
            int c = idx / 96, j = idx % 96;
            float v;
            if (j < 16)       v = p2_q[c*16 + j];
            else if (j < 32)  v = p2_k[c*16 + (j-16)];
            else { int o = (j-32) >> 2, m = (j-32) & 3; v = p2_v[(m*128+c)*16 + o]; }
            d_Wcat2[idx] = v;
        }
        return;
    }

    // blk == 16: zero stats + small precomputes
    for (int i = t; i < 318; i += 256) d_stats[i] = 0.f;

    __shared__ float logit0[4][5], logit1[4][10], logit2[4][10];
    __shared__ float emb0s[4][5];

    if (t == 0) {
        float s = 0.f;
        for (int o = 0; o < 64; o++) s += p0_q[o] * p0_k[o];
        d_C0 = s;
    }
    if (t >= 128 && t < 148) {
        int u = t - 128; int m = u / 5, j = u % 5;
        float la = 0.f, lb = 0.f;
        for (int o = 0; o < 64; o++) {
            la += p0_em[m*64+o] * p0_ea[o];
            lb += p0_em[m*64+o] * p0_eb[o*5+j];
        }
        logit0[m][j] = la + lb;
    }
    if (t < 40) {
        int m = t / 10, kl = t % 10, i = kl / 5, j = kl % 5;
        float la = 0.f, lb = 0.f;
        for (int o = 0; o < 128; o++) {
            la += p1_em[m*128+o] * p1_ea[o*2+i];
            lb += p1_em[m*128+o] * p1_eb[o*5+j];
        }
        logit1[m][kl] = la + lb;
    }
    if (t >= 64 && t < 104) {
        int u = t - 64; int m = u / 10, kl = u % 10, i = kl / 5, j = kl % 5;
        float la = 0.f, lb = 0.f;
        for (int o = 0; o < 16; o++) {
            la += p2_em[m*16+o] * p2_ea[o*2+i];
            lb += p2_em[m*16+o] * p2_eb[o*5+j];
        }
        logit2[m][kl] = la + lb;
    }
    __syncthreads();
    if (t < 5) {
        float mx = -1e30f;
        for (int m = 0; m < 4; m++) mx = fmaxf(mx, logit0[m][t]);
        float e[4], s = 0.f;
        for (int m = 0; m < 4; m++) { e[m] = __expf(logit0[m][t]-mx); s += e[m]; }
        for (int m = 0; m < 4; m++) emb0s[m][t] = e[m] / s;
    }
    if (t >= 32 && t < 42) {
        int kl = t - 32;
        float mx = -1e30f;
        for (int m = 0; m < 4; m++) mx = fmaxf(mx, logit1[m][kl]);
        float e[4], s = 0.f;
        for (int m = 0; m < 4; m++) { e[m] = __expf(logit1[m][kl]-mx); s += e[m]; }
        for (int m = 0; m < 4; m++) d_emb1[m*10+kl] = e[m] / s;
    }
    if (t >= 64 && t < 74) {
        int kl = t - 64;
        float mx = -1e30f;
        for (int m = 0; m < 4; m++) mx = fmaxf(mx, logit2[m][kl]);
        float e[4], s = 0.f;
        for (int m = 0; m < 4; m++) { e[m] = __expf(logit2[m][kl]-mx); s += e[m]; }
        for (int m = 0; m < 4; m++) d_emb2[m*10+kl] = e[m] / s;
    }
    __syncthreads();
    for (int idx = t; idx < 5*64; idx += blockDim.x) {
        int l = idx / 64, o = idx % 64;
        float s = 0.f;
        for (int m = 0; m < 4; m++) s += emb0s[m][l] * p0_v[m*64+o];
        d_Weff0[idx] = s;
    }
}

// ---------------------------------------------------------------------------
// K1: stage0 attention -> g[5] + low-rank BN stats. grid (24,8,2), block 128
// ---------------------------------------------------------------------------
__global__ void k1_stem0(const float* x)
{
    int tid = threadIdx.x;
    int w = blockIdx.x * 128 + tid;
    int h = blockIdx.y, b = blockIdx.z;
    bool valid = (w < 3000);

    float g[5] = {0.f,0.f,0.f,0.f,0.f};
    if (valid) {
        const float* xr = x + (b*8 + h) * 3000;
        float xc = xr[w];
        float C0 = d_C0;
        float xl[5], sc[5];
        float mx = -1e30f;
        #pragma unroll
        for (int l = 0; l < 5; l++) {
            int c = w + l - 2;
            xl[l] = (c >= 0 && c < 3000) ? xr[c] : 0.f;
            sc[l] = xc * xl[l] * C0;
            mx = fmaxf(mx, sc[l]);
        }
        float s = 0.f;
        #pragma unroll
        for (int l = 0; l < 5; l++) { sc[l] = __expf(sc[l]-mx); s += sc[l]; }
        float inv = 1.f / s;
        #pragma unroll
        for (int l = 0; l < 5; l++) g[l] = sc[l] * inv * xl[l];
    }

    float st[20];
    {
        int si = 0;
        #pragma unroll
        for (int l = 0; l < 5; l++) st[si++] = g[l];
        #pragma unroll
        for (int l = 0; l < 5; l++)
            #pragma unroll
            for (int l2 = l; l2 < 5; l2++) st[si++] = g[l]*g[l2];
    }
    #pragma unroll
    for (int i = 0; i < 20; i++)
        #pragma unroll
        for (int off = 16; off; off >>= 1)
            st[i] += __shfl_xor_sync(0xffffffffu, st[i], off);

    __shared__ float red[4][20];
    int lane = tid & 31, wrp = tid >> 5;
    if (lane == 0)
        for (int i = 0; i < 20; i++) red[wrp][i] = st[i];
    __syncthreads();
    if (tid < 20) {
        float v = red[0][tid] + red[1][tid] + red[2][tid] + red[3][tid];
        int slot;
        if (tid < 5) slot = tid;
        else {
            int k = tid - 5, l = 0;
            while (k >= 5 - l) { k -= 5 - l; l++; }
            slot = 5 + l*5 + (l + k);
        }
        atomicAdd(&P_S0[slot], v);
    }

    if (valid && !(h & 1) && !(w & 1)) {
        int p = b*6000 + (h>>1)*1500 + (w>>1);
        #pragma unroll
        for (int l = 0; l < 5; l++) d_g0[l*12000 + p] = g[l];
    }
}

// ---------------------------------------------------------------------------
// K3: stage0 BN + ReLU -> h1 bf16 hi/lo. grid 3000, block 256
// ---------------------------------------------------------------------------
__global__ void k3_h1(const float* g0, const float* b0)
{
    __shared__ float sW[5*64];
    __shared__ float sScale[64], sShift[64];
    int tid = threadIdx.x;
    for (int i = tid; i < 320; i += 256) sW[i] = d_Weff0[i];
    __syncthreads();
    if (tid < 64) {
        int c = tid;
        float Wc[5];
        #pragma unroll
        for (int l = 0; l < 5; l++) Wc[l] = sW[l*64 + c];
        float mn = 0.f, mq = 0.f;
        #pragma unroll
        for (int l = 0; l < 5; l++) {
            mn += P_S0[l] * Wc[l];
            #pragma unroll
            for (int l2 = 0; l2 < 5; l2++) {
                int lo = l < l2 ? l : l2, hi = l < l2 ? l2 : l;
                mq += P_S0[5 + lo*5 + hi] * Wc[l] * Wc[l2];
            }
        }
        float n = 48000.f;
        float mean = mn / n;
        float var  = mq / n - mean*mean;
        float sc = g0[c] * rsqrtf(var + 1e-5f);
        sScale[c] = sc;
        sShift[c] = b0[c] - mean * sc;
    }
    __syncthreads();

    int c = tid & 63;
    int p = blockIdx.x * 4 + (tid >> 6);
    float a = 0.f;
    #pragma unroll
    for (int l = 0; l < 5; l++) a += d_g0[l*12000 + p] * sW[l*64 + c];
    float y = fmaxf(fmaf(a, sScale[c], sShift[c]), 0.f);
    __nv_bfloat16 hi = __float2bfloat16_rn(y);
    d_h1h[p*64 + c] = hi;
    d_h1l[p*64 + c] = __float2bfloat16_rn(y - __bfloat162float(hi));
}

// ---------------------------------------------------------------------------
// K4: stage1 qkv GEMM (real rows only, M'=12032), bf16 3-term + ldmatrix,
// 4x2 warp layout. q/k stored fp32 to d_qk1, v stored fp16 to d_v1.
// Zero-fills hp=0 pad rows of both. grid (94, 12), block 256.
// ---------------------------------------------------------------------------
#define K4_SMEM ((128*72 + 128*72 + 64*72 + 64*72) * 2)

__global__ void k4_gemm1()
{
    extern __shared__ __nv_bfloat16 sh[];
    __nv_bfloat16* Ah = sh;
    __nv_bfloat16* Al = Ah + 128*72;
    __nv_bfloat16* Bh = Al + 128*72;
    __nv_bfloat16* Bl = Bh + 64*72;

    int tid = threadIdx.x;
    int rowBase = blockIdx.x * 128;
    int colBase = blockIdx.y * 64;

    // zero-fill hp=0 pad rows: 192512 float4 (qk) + 192512 uint4 (v)
    {
        int idx = (blockIdx.y * 94 + blockIdx.x) * 256 + tid;
        if (idx < 192512) {
            float4 z4 = make_float4(0.f,0.f,0.f,0.f);
            uint4 zu = make_uint4(0,0,0,0);
            int fidx = idx * 4;
            int row = fidx >> 8, col = fidx & 255;
            int b = row >= 1504; int wp = row - b*1504;
            *(float4*)&d_qk1[((size_t)(b*9024 + wp))*256 + col] = z4;
            int eidx = idx * 8;
            int vrow = eidx >> 9, vcol = eidx & 511;
            int b2 = vrow >= 1504; int wp2 = vrow - b2*1504;
            *(uint4*)&d_v1[((size_t)(b2*9024 + wp2))*512 + vcol] = zu;
        }
    }

    {
        int r = tid >> 1;
        int half = (tid & 1) * 32;
        int prow = rowBase + r;
        int b = prow / 6016; int rem = prow % 6016;
        int hp = 1 + rem / 1504; int wp = rem % 1504;
        bool valid = (wp >= 2 && wp < 1502);
        __nv_bfloat16* dh = Ah + r*72 + half;
        __nv_bfloat16* dl = Al + r*72 + half;
        if (valid) {
            int pos = ((b*4 + (hp-1))*1500 + (wp-2))*64 + half;
            const uint4* sH = (const uint4*)(d_h1h + pos);
            const uint4* sL = (const uint4*)(d_h1l + pos);
            #pragma unroll
            for (int u = 0; u < 4; u++) {
                ((uint4*)dh)[u] = sH[u];
                ((uint4*)dl)[u] = sL[u];
            }
        } else {
            uint4 z = make_uint4(0,0,0,0);
            #pragma unroll
            for (int u = 0; u < 4; u++) { ((uint4*)dh)[u] = z; ((uint4*)dl)[u] = z; }
        }
    }
    {
        int n = tid >> 2;
        int seg = (tid & 3) * 16;
        const uint4* sH = (const uint4*)(d_W1bh + (colBase + n)*64 + seg);
        const uint4* sL = (const uint4*)(d_W1bl + (colBase + n)*64 + seg);
        uint4* dh = (uint4*)(Bh + n*72 + seg);
        uint4* dl = (uint4*)(Bl + n*72 + seg);
        dh[0] = sH[0]; dh[1] = sH[1];
        dl[0] = sL[0]; dl[1] = sL[1];
    }
    __syncthreads();

    int lane = tid & 31, wid = tid >> 5;
    int g = lane >> 2, tg = lane & 3;
    int mr   = (wid >> 1) * 32;
    int ncol = (wid & 1) * 32;

    int arow = (lane < 16) ? lane : (lane - 16);
    int acol = (lane < 16) ? 0 : 8;
    uint32_t aAddrH[2], aAddrL[2];
    #pragma unroll
    for (int mt = 0; mt < 2; mt++) {
        aAddrH[mt] = (uint32_t)__cvta_generic_to_shared(Ah + (mr + mt*16 + arow)*72 + acol);
        aAddrL[mt] = (uint32_t)__cvta_generic_to_shared(Al + (mr + mt*16 + arow)*72 + acol);
    }
    int brow = (lane & 7) + ((lane >> 4) << 3);
    int bcol = ((lane >> 3) & 1) * 8;
    uint32_t bAddrH[2], bAddrL[2];
    #pragma unroll
    for (int pr = 0; pr < 2; pr++) {
        bAddrH[pr] = (uint32_t)__cvta_generic_to_shared(Bh + (ncol + pr*16 + brow)*72 + bcol);
        bAddrL[pr] = (uint32_t)__cvta_generic_to_shared(Bl + (ncol + pr*16 + brow)*72 + bcol);
    }

    float4 acc[2][4];
    #pragma unroll
    for (int i = 0; i < 2; i++)
        #pragma unroll
        for (int j = 0; j < 4; j++) acc[i][j] = make_float4(0.f,0.f,0.f,0.f);

    #pragma unroll
    for (int ks = 0; ks < 4; ks++) {
        uint32_t koff = ks * 32;
        uint32_t ah[2][4], al[2][4], bh[2][4], bl[2][4];
        #pragma unroll
        for (int mt = 0; mt < 2; mt++) {
            ldsm_x4(ah[mt][0],ah[mt][1],ah[mt][2],ah[mt][3], aAddrH[mt] + koff);
            ldsm_x4(al[mt][0],al[mt][1],al[mt][2],al[mt][3], aAddrL[mt] + koff);
        }
        #pragma unroll
        for (int pr = 0; pr < 2; pr++) {
            ldsm_x4(bh[pr][0],bh[pr][1],bh[pr][2],bh[pr][3], bAddrH[pr] + koff);
            ldsm_x4(bl[pr][0],bl[pr][1],bl[pr][2],bl[pr][3], bAddrL[pr] + koff);
        }
        #pragma unroll
        for (int mt = 0; mt < 2; mt++)
            #pragma unroll
            for (int pr = 0; pr < 2; pr++) {
                mma_bf16(acc[mt][2*pr  ], ah[mt][0],ah[mt][1],ah[mt][2],ah[mt][3], bh[pr][0],bh[pr][1]);
                mma_bf16(acc[mt][2*pr  ], ah[mt][0],ah[mt][1],ah[mt][2],ah[mt][3], bl[pr][0],bl[pr][1]);
                mma_bf16(acc[mt][2*pr  ], al[mt][0],al[mt][1],al[mt][2],al[mt][3], bh[pr][0],bh[pr][1]);
                mma_bf16(acc[mt][2*pr+1], ah[mt][0],ah[mt][1],ah[mt][2],ah[mt][3], bh[pr][2],bh[pr][3]);
                mma_bf16(acc[mt][2*pr+1], ah[mt][0],ah[mt][1],ah[mt][2],ah[mt][3], bl[pr][2],bl[pr][3]);
                mma_bf16(acc[mt][2*pr+1], al[mt][0],al[mt][1],al[mt][2],al[mt][3], bh[pr][2],bh[pr][3]);
            }
    }

    bool isQK = (colBase < 256);
    #pragma unroll
    for (int mt = 0; mt < 2; mt++) {
        #pragma unroll
        for (int half = 0; half < 2; half++) {
            int prow = rowBase + mr + mt*16 + half*8 + g;
            int b = prow / 6016; int rem = prow % 6016;
            int hp = 1 + rem / 1504; int wp = rem % 1504;
            size_t orow = (size_t)(b*6 + hp)*1504 + wp;
            #pragma unroll
            for (int j = 0; j < 4; j++) {
                int col = colBase + ncol + j*8 + tg*2;
                float2 v = half ? make_float2(acc[mt][j].z, acc[mt][j].w)
                                : make_float2(acc[mt][j].x, acc[mt][j].y);
                if (isQK) {
                    *(float2*)&d_qk1[orow*256 + col] = v;
                } else {
                    __half2 hv;
                    hv.x = __float2half_rn(v.x);
                    hv.y = __float2half_rn(v.y);
                    *(__half2*)&d_v1[orow*512 + (col - 256)] = hv;
                }
            }
        }
    }
}

// ---------------------------------------------------------------------------
// K5: stage1 attention combine, smem-staged q(fp32)/k(fp32)/v(fp16) window.
// 10 positions/block, 512 threads. grid (150, 4, 2).
// smem: sq[10][128] f32 + sk[28][128] f32 + sv[28][512] fp16 = 48128 B
// ---------------------------------------------------------------------------
#define K5_SMEM ((10*128 + 28*128) * 4 + 28*512*2)

__global__ void k5_attn1()
{
    extern __shared__ float sm5[];
    float* sq = sm5;                               // [10][128]
    float* sk = sm5 + 10*128;                      // [28][128]
    __half* sv = (__half*)(sm5 + 10*128 + 28*128); // [28][512]

    int w0 = blockIdx.x * 10, h = blockIdx.y, b = blockIdx.z;
    int tid = threadIdx.x, lane = tid & 31, wrp = tid >> 5;  // 16 warps
    __shared__ float ssc[10][10];
    __shared__ float cm4[10][40];

    const float* qkbase = d_qk1 + (size_t)b * 6 * 1504 * 256;
    const __half* vbase = d_v1 + (size_t)b * 6 * 1504 * 512;

    // stage q: 10 rows x 32 float4 = 320
    for (int idx = tid; idx < 320; idx += 512) {
        int p = idx >> 5, c4 = idx & 31;
        ((float4*)sq)[p*32 + c4] =
            *(const float4*)(qkbase + ((h+1)*1504 + (w0+2+p))*256 + c4*4);
    }
    // stage k: 28 rows x 32 float4 = 896
    for (int idx = tid; idx < 896; idx += 512) {
        int r = idx >> 5, c4 = idx & 31;
        int i = r / 14, jj = r % 14;
        ((float4*)(sk + r*128))[c4] =
            *(const float4*)(qkbase + ((h+i)*1504 + (w0+jj))*256 + 128 + c4*4);
    }
    // stage v: 28 rows x 64 uint4 (8 fp16 each) = 1792
    for (int idx = tid; idx < 1792; idx += 512) {
        int r = idx >> 6, c4 = idx & 63;
        int i = r / 14, jj = r % 14;
        ((uint4*)(sv + r*512))[c4] =
            *(const uint4*)(vbase + ((h+i)*1504 + (w0+jj))*512 + c4*8);
    }
    __syncthreads();

    for (int pair = wrp; pair < 100; pair += 16) {
        int p = pair / 10, kl = pair % 10;
        int i = kl / 5, j = kl % 5;
        float4 q4 = ((const float4*)(sq + p*128))[lane];
        float4 k4 = ((const float4*)(sk + (i*14 + p + j)*128))[lane];
        float s = q4.x*k4.x + q4.y*k4.y + q4.z*k4.z + q4.w*k4.w;
        #pragma unroll
        for (int off = 16; off; off >>= 1) s += __shfl_xor_sync(0xffffffffu, s, off);
        if (lane == 0) ssc[p][kl] = s;
    }
    __syncthreads();
    if (tid < 10) {
        float mx = -1e30f;
        #pragma unroll
        for (int kl = 0; kl < 10; kl++) mx = fmaxf(mx, ssc[tid][kl]);
        float e[10], s = 0.f;
        #pragma unroll
        for (int kl = 0; kl < 10; kl++) { e[kl] = __expf(ssc[tid][kl]-mx); s += e[kl]; }
        float inv = 1.f / s;
        #pragma unroll
        for (int kl = 0; kl < 10; kl++) {
            float a = e[kl] * inv;
            #pragma unroll
            for (int m = 0; m < 4; m++) cm4[tid][kl*4+m] = a * d_emb1[m*10+kl];
        }
    }
    __syncthreads();

    int o = tid & 127;
    int ph = tid >> 7;
    float s1 = 0.f, s2 = 0.f;
    for (int p = ph; p < 10; p += 4) {
        const float* cw = cm4[p];
        float acc = 0.f;
        #pragma unroll
        for (int kl = 0; kl < 10; kl++) {
            int i = kl / 5, j = kl % 5;
            uint2 pv = *(const uint2*)(sv + (i*14 + p + j)*512 + o*4);
            float2 v01 = __half22float2(*(const __half2*)&pv.x);
            float2 v23 = __half22float2(*(const __half2*)&pv.y);
            acc += cw[kl*4]*v01.x + cw[kl*4+1]*v01.y + cw[kl*4+2]*v23.x + cw[kl*4+3]*v23.y;
        }
        s1 += acc; s2 += acc*acc;
        if (!(h & 1) && !((w0+p) & 1))
            d_o1raw[((b*2 + (h>>1))*750 + ((w0+p)>>1))*128 + o] = acc;
    }
    atomicAdd(&P_SUM1[o], s1);
    atomicAdd(&P_SUMSQ1[o], s2);
}

// ---------------------------------------------------------------------------
// K8: stage2 qkv GEMM, ILP-split dots, 8 positions/block.
// grid (95, 2, 2), block 256.
// ---------------------------------------------------------------------------
#define K8_SMEM ((128*96 + 8*128) * 4)

__global__ void k8_gemm2(const float* g1, const float* b1)
{
    extern __shared__ float sm8[];
    float* sWt = sm8;               // [128][96]
    float* sa  = sm8 + 128*96;      // [8][128]
    __shared__ float sScale[128], sShift[128];

    int t = threadIdx.x;
    int hp = blockIdx.y, b = blockIdx.z;
    int W0 = blockIdx.x * 8;

    if (t < 128) {
        float n = 12000.f;
        float mean = P_SUM1[t] / n;
        float var  = P_SUMSQ1[t] / n - mean*mean;
        float sc = g1[t] * rsqrtf(var + 1e-5f);
        sScale[t] = sc;
        sShift[t] = b1[t] - mean*sc;
    }
    for (int idx = t; idx < 3072; idx += 256)
        ((float4*)sWt)[idx] = ((const float4*)d_Wcat2)[idx];
    __syncthreads();

    for (int idx = t; idx < 1024; idx += 256) {
        int ps = idx >> 7, i = idx & 127;
        int wp = W0 + ps;
        float v = 0.f;
        if (wp >= 2 && wp < 752) {
            float raw = d_o1raw[(((b*2 + hp)*750) + (wp-2))*128 + i];
            v = fmaxf(fmaf(raw, sScale[i], sShift[i]), 0.f);
        }
        sa[ps*128 + i] = v;
    }
    __syncthreads();

    #pragma unroll
    for (int k = 0; k < 3; k++) {
        int pair = t + k*256;
        int ps = pair / 96, o = pair - (pair/96)*96;
        int wp = W0 + ps;
        if (wp >= 754) continue;
        const float* av = sa + ps*128;
        float a0 = 0.f, a1 = 0.f, a2 = 0.f, a3 = 0.f;
        #pragma unroll
        for (int c = 0; c < 32; c++) {
            a0 = fmaf(av[c],     sWt[c*96 + o],        a0);
            a1 = fmaf(av[c+32],  sWt[(c+32)*96 + o],   a1);
            a2 = fmaf(av[c+64],  sWt[(c+64)*96 + o],   a2);
            a3 = fmaf(av[c+96],  sWt[(c+96)*96 + o],   a3);
        }
        d_qkv2[(((b*2 + hp)*754) + wp)*96 + o] = (a0 + a1) + (a2 + a3);
    }
}

// ---------------------------------------------------------------------------
// K9: stage2 attention combine, warp per position. grid (188, 2), block 128
// ---------------------------------------------------------------------------
__global__ void k9_attn2()
{
    __shared__ float semb[40];
    int tid = threadIdx.x;
    if (tid < 40) { int kl = tid >> 2, m = tid & 3; semb[tid] = d_emb2[m*10+kl]; }
    __syncthreads();

    int lane = tid & 31, wrp = tid >> 5;
    int w = blockIdx.x * 4 + wrp, b = blockIdx.y;
    if (w >= 750) return;

    const float* base = d_qkv2 + (size_t)b * 2 * 754 * 96;
    const float* qp = base + (w + 2) * 96;
    float qv = (lane < 16) ? qp[lane] : 0.f;

    float scl[10];
    float mx = -1e30f;
    #pragma unroll
    for (int kl = 0; kl < 10; kl++) {
        int i = kl / 5, j = kl % 5;
        const float* kp = base + (i*754 + (w+j))*96 + 16;
        float pr = (lane < 16) ? qv * kp[lane] : 0.f;
        #pragma unroll
        for (int off = 8; off; off >>= 1) pr += __shfl_xor_sync(0xffffffffu, pr, off);
        scl[kl] = pr;
        mx = fmaxf(mx, pr);
    }
    float s = 0.f;
    #pragma unroll
    for (int kl = 0; kl < 10; kl++) { scl[kl] = __expf(scl[kl]-mx); s += scl[kl]; }
    float inv = 1.f / s;
    if (lane < 16) {
        float acc = 0.f;
        #pragma unroll
        for (int kl = 0; kl < 10; kl++) {
            int i = kl / 5, j = kl % 5;
            float4 v = *(const float4*)(base + (i*754 + (w+j))*96 + 32 + lane*4);
            float aw = scl[kl] * inv;
            acc += aw * (semb[kl*4]*v.x + semb[kl*4+1]*v.y + semb[kl*4+2]*v.z + semb[kl*4+3]*v.w);
        }
        d_out2[(b*750 + w)*16 + lane] = acc;
        atomicAdd(&P_SUM2[lane], acc);
        atomicAdd(&P_SUMSQ2[lane], acc*acc);
    }
}

// ---------------------------------------------------------------------------
// K11: stage2 BN + ReLU + AvgPool(1,56) -> out. grid (13,16,2), block 64
// ---------------------------------------------------------------------------
__global__ void k11_final(float* out, const float* g2, const float* b2)
{
    int n = blockIdx.x, c = blockIdx.y, b = blockIdx.z;
    int t = threadIdx.x;
    float nn = 1500.f;
    float mean = P_SUM2[c] / nn;
    float var  = P_SUMSQ2[c] / nn - mean*mean;
    float sc = g2[c] * rsqrtf(var + 1e-5f);
    float sf = b2[c] - mean * sc;

    float v = 0.f;
    if (t < 56) {
        float raw = d_out2[(b*750 + n*56 + t)*16 + c];
        v = fmaxf(fmaf(raw, sc, sf), 0.f);
    }
    __shared__ float shm[64];
    shm[t] = v;
    __syncthreads();
    for (int st = 32; st; st >>= 1) {
        if (t < st) shm[t] += shm[t+st];
        __syncthreads();
    }
    if (t == 0) out[(b*16 + c)*13 + n] = shm[0] * (1.f/56.f);
}

// ---------------------------------------------------------------------------
extern "C" void kernel_launch(void* const* d_in, const int* in_sizes, int n_in,
                              void* d_out, int out_size)
{
    const float* x     = (const float*)d_in[0];
    const float* p0_q  = (const float*)d_in[1];
    const float* p0_k  = (const float*)d_in[2];
    const float* p0_v  = (const float*)d_in[3];
    const float* p0_ea = (const float*)d_in[4];
    const float* p0_eb = (const float*)d_in[5];
    const float* p0_em = (const float*)d_in[6];
    const float* p0_g  = (const float*)d_in[7];
    const float* p0_b  = (const float*)d_in[8];
    const float* p1_q  = (const float*)d_in[9];
    const float* p1_k  = (const float*)d_in[10];
    const float* p1_v  = (const float*)d_in[11];
    const float* p1_ea = (const float*)d_in[12];
    const float* p1_eb = (const float*)d_in[13];
    const float* p1_em = (const float*)d_in[14];
    const float* p1_g  = (const float*)d_in[15];
    const float* p1_b  = (const float*)d_in[16];
    const float* p2_q  = (const float*)d_in[17];
    const float* p2_k  = (const float*)d_in[18];
    const float* p2_v  = (const float*)d_in[19];
    const float* p2_ea = (const float*)d_in[20];
    const float* p2_eb = (const float*)d_in[21];
    const float* p2_em = (const float*)d_in[22];
    const float* p2_g  = (const float*)d_in[23];
    const float* p2_b  = (const float*)d_in[24];
    float* out = (float*)d_out;

    static int smem_set = 0;
    if (!smem_set) {
        cudaFuncSetAttribute(k4_gemm1, cudaFuncAttributeMaxDynamicSharedMemorySize, K4_SMEM);
        cudaFuncSetAttribute(k5_attn1, cudaFuncAttributeMaxDynamicSharedMemorySize, K5_SMEM);
        cudaFuncSetAttribute(k8_gemm2, cudaFuncAttributeMaxDynamicSharedMemorySize, K8_SMEM);
        smem_set = 1;
    }

    k0_pre<<<17, 256>>>(p0_q, p0_k, p0_v, p0_ea, p0_eb, p0_em,
                        p1_q, p1_k, p1_v, p1_ea, p1_eb, p1_em,
                        p2_q, p2_k, p2_v, p2_ea, p2_eb, p2_em);
    k1_stem0<<<dim3(24, 8, 2), 128>>>(x);
    k3_h1<<<3000, 256>>>(p0_g, p0_b);
    k4_gemm1<<<dim3(94, 12), 256, K4_SMEM>>>();
    k5_attn1<<<dim3(150, 4, 2), 512, K5_SMEM>>>();
    k8_gemm2<<<dim3(95, 2, 2), 256, K8_SMEM>>>(p1_g, p1_b);
    k9_attn2<<<dim3(188, 2), 128>>>();
    k11_final<<<dim3(13, 16, 2), 64>>>(out, p2_g, p2_b);
}